// round 16
// baseline (speedup 1.0000x reference)
#include <cuda_runtime.h>
#include <cuda_fp16.h>
#include <math.h>
#include <stdint.h>

// Problem shape (fixed by the dataset): B=4, T=2048, D=512, H=8, Hd=64, FFN=2048
#define T_SEQ   2048
#define DIM     512
#define NHEAD   8
#define HDIM    64
#define FFN_DIM 2048
#define MAX_BT  8192

// ======================= helpers =======================
__device__ __forceinline__ uint32_t smem_u32(const void* p) {
    uint32_t a;
    asm("{ .reg .u64 t; cvta.to.shared.u64 t, %1; cvt.u32.u64 %0, t; }" : "=r"(a) : "l"(p));
    return a;
}
__device__ __forceinline__ void cp16(uint32_t s, const void* g) {
    asm volatile("cp.async.ca.shared.global [%0], [%1], 16;" :: "r"(s), "l"(g));
}
#define CP_COMMIT() asm volatile("cp.async.commit_group;" ::: "memory")
#define CP_WAIT1()  asm volatile("cp.async.wait_group 1;" ::: "memory")

__device__ __forceinline__ void ldsm4(uint32_t* r, uint32_t addr) {
    asm volatile("ldmatrix.sync.aligned.m8n8.x4.shared.b16 {%0,%1,%2,%3}, [%4];"
        : "=r"(r[0]), "=r"(r[1]), "=r"(r[2]), "=r"(r[3]) : "r"(addr));
}
// f16 inputs, f32 accumulate (attention uses this)
__device__ __forceinline__ void mma_f32(float* c, const uint32_t* a, const uint32_t* b) {
    asm volatile(
        "mma.sync.aligned.m16n8k16.row.col.f32.f16.f16.f32 "
        "{%0,%1,%2,%3}, {%4,%5,%6,%7}, {%8,%9}, {%0,%1,%2,%3};"
        : "+f"(c[0]), "+f"(c[1]), "+f"(c[2]), "+f"(c[3])
        : "r"(a[0]), "r"(a[1]), "r"(a[2]), "r"(a[3]), "r"(b[0]), "r"(b[1]));
}
// f16 accumulate, zero C (chunk start)
__device__ __forceinline__ void mma_f16_zc(uint32_t* c, const uint32_t* a, const uint32_t* b) {
    asm volatile(
        "mma.sync.aligned.m16n8k16.row.col.f16.f16.f16.f16 "
        "{%0,%1}, {%2,%3,%4,%5}, {%6,%7}, {%8,%8};"
        : "=r"(c[0]), "=r"(c[1])
        : "r"(a[0]), "r"(a[1]), "r"(a[2]), "r"(a[3]), "r"(b[0]), "r"(b[1]), "r"(0u));
}
// f16 accumulate, chained C
__device__ __forceinline__ void mma_f16(uint32_t* c, const uint32_t* a, const uint32_t* b) {
    asm volatile(
        "mma.sync.aligned.m16n8k16.row.col.f16.f16.f16.f16 "
        "{%0,%1}, {%2,%3,%4,%5}, {%6,%7}, {%0,%1};"
        : "+r"(c[0]), "+r"(c[1])
        : "r"(a[0]), "r"(a[1]), "r"(a[2]), "r"(a[3]), "r"(b[0]), "r"(b[1]));
}

// ======================= scratch =======================
__device__ __half g_wqkvT[3 * DIM * DIM];
__device__ __half g_woutT[DIM * DIM];
__device__ __half g_w1T[FFN_DIM * DIM];
__device__ __half g_w2T[DIM * FFN_DIM];
__device__ __half g_xn[MAX_BT * DIM];
__device__ __half g_ctx[MAX_BT * DIM];
__device__ __half g_hh[MAX_BT * FFN_DIM];
__device__ __half g_qkvh[MAX_BT * 3 * DIM];
__device__ float g_x1[MAX_BT * DIM];

// ======================= fused weight prep: all 4 weights, one launch ============
__global__ void wprep_all(const float* __restrict__ W0, __half* __restrict__ T0,
                          const float* __restrict__ W1, __half* __restrict__ T1,
                          const float* __restrict__ W2, __half* __restrict__ T2,
                          const float* __restrict__ W3, __half* __restrict__ T3) {
    __shared__ float t[32][33];
    const int gid = blockIdx.x;
    const float* W; __half* T; int K, N, lb, gx;
    if (gid < 768)        { W = W0; T = T0; K = 512;  N = 1536; lb = gid;        gx = 48; }
    else if (gid < 1024)  { W = W1; T = T1; K = 512;  N = 512;  lb = gid - 768;  gx = 16; }
    else if (gid < 2048)  { W = W2; T = T2; K = 512;  N = 2048; lb = gid - 1024; gx = 64; }
    else                  { W = W3; T = T3; K = 2048; N = 512;  lb = gid - 2048; gx = 16; }
    const int n0 = (lb % gx) * 32, k0 = (lb / gx) * 32;
    const int tx = threadIdx.x, ty = threadIdx.y;
    #pragma unroll
    for (int i = 0; i < 4; ++i)
        t[ty + i * 8][tx] = W[(size_t)(k0 + ty + i * 8) * N + n0 + tx];
    __syncthreads();
    #pragma unroll
    for (int i = 0; i < 4; ++i)
        T[(size_t)(n0 + ty + i * 8) * K + k0 + tx] = __float2half_rn(t[tx][ty + i * 8]);
}

// ======================= rmsnorm -> f16 =======================
__global__ void rmsnorm_h_kernel(const float* __restrict__ x,
                                 const float* __restrict__ w,
                                 __half* __restrict__ y) {
    const int row = blockIdx.x;
    const int tid = threadIdx.x;  // 128
    const float4 v = reinterpret_cast<const float4*>(x + (size_t)row * DIM)[tid];
    float ss = v.x * v.x + v.y * v.y + v.z * v.z + v.w * v.w;
    #pragma unroll
    for (int off = 16; off > 0; off >>= 1)
        ss += __shfl_xor_sync(0xFFFFFFFFu, ss, off);
    __shared__ float red[4];
    const int warp = tid >> 5, lane = tid & 31;
    if (lane == 0) red[warp] = ss;
    __syncthreads();
    const float r = rsqrtf((red[0] + red[1] + red[2] + red[3]) * (1.0f / DIM) + 1e-6f);
    const float4 wv = reinterpret_cast<const float4*>(w)[tid];
    const size_t e = (size_t)row * DIM + tid * 4;
    *reinterpret_cast<__half2*>(y + e) =
        __floats2half2_rn(v.x * r * wv.x, v.y * r * wv.y);
    *reinterpret_cast<__half2*>(y + e + 2) =
        __floats2half2_rn(v.z * r * wv.z, v.w * r * wv.w);
}

// ======================= mma.sync GEMM (f16-acc K32 chunks -> f32 promote) =======
// C[M,N] = sum_k A[M,K]*B^T[N,K]. 128x128 block tile, 8 warps (64x32), K-slab 64,
// 3-stage cp.async, single sync/slab, 2 CTAs/SM.
// Per K32 chunk: 2 chained f16-acc mma (zero C start), then promote into f32 acc.
// EPI: 1 +bias+resid fp32 C; 2 +bias, gelu -> f16 Ch; 3 plain -> f16 Ch
#define PADK   72
#define MATB   (128 * 144)
#define STAGEB (2 * MATB)
#define NSTAGE 3
#define GEMM_DSMEM (NSTAGE * STAGEB)

template <int EPI>
__global__ __launch_bounds__(256, 2)
void gemm_mma(const __half* __restrict__ A, const __half* __restrict__ Bw,
              const float* __restrict__ bias, const float* __restrict__ R,
              float* __restrict__ C, __half* __restrict__ Ch,
              int M, int N, int K) {
    extern __shared__ char dsm[];
    const uint32_t sm0 = smem_u32(dsm);
    const int tid = threadIdx.x;
    const int wid = tid >> 5;
    const int lane = tid & 31;
    const int wm = wid & 1;
    const int wn = wid >> 1;
    const int bm = blockIdx.y * 128;
    const int bn = blockIdx.x * 128;

    const int NS = K / 64;

    auto load_slab = [&](int s, int buf) {
        const uint32_t st = sm0 + (uint32_t)buf * STAGEB;
        const int k0 = s * 64;
        #pragma unroll
        for (int i = 0; i < 4; ++i) {
            const int idx = tid + i * 256;
            const int row = idx >> 3;
            const int c   = idx & 7;
            const uint32_t so = (uint32_t)(row * 144 + c * 16);
            cp16(st + 0 * MATB + so, A  + (size_t)(bm + row) * K + k0 + c * 8);
            cp16(st + 1 * MATB + so, Bw + (size_t)(bn + row) * K + k0 + c * 8);
        }
    };

    float acc[4][4][4] = {};

    load_slab(0, 0); CP_COMMIT();
    if (NS > 1) load_slab(1, 1);
    CP_COMMIT();

    const uint32_t aRow = (uint32_t)(wm * 64 + (lane & 15));
    const uint32_t aKo  = (uint32_t)((lane >> 4) * 8);
    const uint32_t bRow = (uint32_t)(wn * 32 + (lane & 7) + ((lane >> 4) << 3));
    const uint32_t bKo  = (uint32_t)(((lane >> 3) & 1) * 8);

    int cbuf = 0, lbuf = 2;
    for (int s = 0; s < NS; ++s) {
        CP_WAIT1();
        __syncthreads();
        if (s + 2 < NS) load_slab(s + 2, lbuf);
        CP_COMMIT();
        const uint32_t st = sm0 + (uint32_t)cbuf * STAGEB;
        if (++lbuf == NSTAGE) lbuf = 0;
        if (++cbuf == NSTAGE) cbuf = 0;

        #pragma unroll
        for (int kp = 0; kp < 64; kp += 32) {
            // B fragments for both k16 halves of this K32 chunk
            uint32_t bf[2][2][4];
            #pragma unroll
            for (int hh = 0; hh < 2; ++hh)
                #pragma unroll
                for (int g = 0; g < 2; ++g) {
                    const uint32_t off = ((bRow + g * 16) * PADK + kp + hh * 16 + bKo) * 2;
                    ldsm4(bf[hh][g], st + 1 * MATB + off);
                }
            #pragma unroll
            for (int mi = 0; mi < 4; ++mi) {
                uint32_t a0[4], a1[4];
                ldsm4(a0, st + ((aRow + mi * 16) * PADK + kp + aKo) * 2);
                ldsm4(a1, st + ((aRow + mi * 16) * PADK + kp + 16 + aKo) * 2);
                #pragma unroll
                for (int ni = 0; ni < 4; ++ni) {
                    const int g = ni >> 1, sub = (ni & 1) * 2;
                    uint32_t t[2];
                    mma_f16_zc(t, a0, &bf[0][g][sub]);
                    mma_f16(t, a1, &bf[1][g][sub]);
                    const __half2* hp = reinterpret_cast<const __half2*>(t);
                    const float2 f0 = __half22float2(hp[0]);
                    const float2 f1 = __half22float2(hp[1]);
                    acc[mi][ni][0] += f0.x;
                    acc[mi][ni][1] += f0.y;
                    acc[mi][ni][2] += f1.x;
                    acc[mi][ni][3] += f1.y;
                }
            }
        }
    }

    // epilogue
    const int cbase = bn + wn * 32 + (lane & 3) * 2;
    const int rbase = bm + wm * 64 + (lane >> 2);
    #pragma unroll
    for (int mi = 0; mi < 4; ++mi) {
        #pragma unroll
        for (int ni = 0; ni < 4; ++ni) {
            const int col = cbase + ni * 8;
            #pragma unroll
            for (int half = 0; half < 2; ++half) {
                const int row = rbase + mi * 16 + half * 8;
                float v0 = acc[mi][ni][half * 2 + 0];
                float v1 = acc[mi][ni][half * 2 + 1];
                if (EPI == 1) {
                    const float2 rv = *(const float2*)(R + (size_t)row * N + col);
                    v0 += bias[col]     + rv.x;
                    v1 += bias[col + 1] + rv.y;
                    *(float2*)(C + (size_t)row * N + col) = {v0, v1};
                } else if (EPI == 2) {
                    const float t0 = v0 + bias[col];
                    const float t1 = v1 + bias[col + 1];
                    const float g0 = 0.5f * t0 * (1.0f + erff(t0 * 0.70710678118654752f));
                    const float g1 = 0.5f * t1 * (1.0f + erff(t1 * 0.70710678118654752f));
                    *reinterpret_cast<__half2*>(Ch + (size_t)row * N + col) =
                        __floats2half2_rn(g0, g1);
                } else {
                    *reinterpret_cast<__half2*>(Ch + (size_t)row * N + col) =
                        __floats2half2_rn(v0, v1);
                }
            }
        }
    }
}

// ======================= flash-style banded attention (tensor-core) ==============
// Unchanged from round 14 (passed: 44.6us).
#define AQ_OFF  0
#define AK_OFF  18432
#define AV_OFF  (18432 + 36864)
#define VT_PAD  264
#define ATT_DSMEM (AV_OFF + 64 * VT_PAD * 2)

__global__ __launch_bounds__(256)
void attn_kernel(const __half* __restrict__ qkv,
                 __half* __restrict__ ctx,
                 const int* __restrict__ csp, int T) {
    extern __shared__ char dsm[];
    __half* Qs = (__half*)(dsm + AQ_OFF);
    __half* Ks = (__half*)(dsm + AK_OFF);
    __half* Vt = (__half*)(dsm + AV_OFF);

    const int cs = min(*csp, 64);
    const int tid = threadIdx.x;
    const int wid = tid >> 5;
    const int lane = tid & 31;
    const int q0 = blockIdx.x * 128;
    const int h = blockIdx.y;
    const int b = blockIdx.z;

    const int jlo = max(q0 - cs, 0);
    const int jhi = min(q0 + 127 + cs, T - 1);
    const int nk = jhi - jlo + 1;

    const size_t gbase = (size_t)(b * T) * (3 * DIM) + h * HDIM;

    const __half2 qsc = __float2half2_rn(0.125f);
    for (int i = tid; i < 128 * 8; i += 256) {
        const int row = i >> 3, c = i & 7;
        const __half2* src = (const __half2*)(qkv + gbase + (size_t)(q0 + row) * (3 * DIM) + c * 8);
        __half2* dst = (__half2*)(Qs + row * 72 + c * 8);
        #pragma unroll
        for (int u = 0; u < 4; ++u) dst[u] = __hmul2(src[u], qsc);
    }
    for (int i = tid; i < 256 * 8; i += 256) {
        const int row = i >> 3, c = i & 7;
        uint4 val = {0u, 0u, 0u, 0u};
        if (row < nk)
            val = *(const uint4*)(qkv + gbase + (size_t)(jlo + row) * (3 * DIM) + DIM + c * 8);
        *(uint4*)(Ks + row * 72 + c * 8) = val;
    }
    for (int i = tid; i < 8192; i += 256) {
        const int key = i & 255, dp = i >> 8;
        __half2 v = __floats2half2_rn(0.0f, 0.0f);
        if (key < nk)
            v = *(const __half2*)(qkv + gbase + (size_t)(jlo + key) * (3 * DIM) + 2 * DIM + dp * 2);
        Vt[(2 * dp)     * VT_PAD + key] = __low2half(v);
        Vt[(2 * dp + 1) * VT_PAD + key] = __high2half(v);
    }
    __syncthreads();

    const uint32_t sQ = smem_u32(Qs), sK = smem_u32(Ks), sV = smem_u32(Vt);

    int nb = q0 + wid * 16 - cs - jlo;
    nb = (nb < 0 ? 0 : nb) & ~7;

    const uint32_t aRow = (uint32_t)(wid * 16 + (lane & 15));
    const uint32_t aKo  = (uint32_t)((lane >> 4) * 8);
    uint32_t aq[4][4];
    #pragma unroll
    for (int kk = 0; kk < 4; ++kk)
        ldsm4(aq[kk], sQ + (aRow * 72 + kk * 16 + aKo) * 2);

    const uint32_t bR  = (uint32_t)((lane & 7) + ((lane >> 4) << 3));
    const uint32_t bKo = (uint32_t)(((lane >> 3) & 1) * 8);

    float sacc[18][4] = {};
    #pragma unroll
    for (int ng = 0; ng < 9; ++ng) {
        #pragma unroll
        for (int kk = 0; kk < 4; ++kk) {
            uint32_t bf[4];
            ldsm4(bf, sK + ((uint32_t)(nb + ng * 16 + bR) * 72 + kk * 16 + bKo) * 2);
            mma_f32(sacc[ng * 2],     aq[kk], &bf[0]);
            mma_f32(sacc[ng * 2 + 1], aq[kk], &bf[2]);
        }
    }

    const int r0 = q0 + wid * 16 + (lane >> 2);
    const int r1 = r0 + 8;
    const int cb = jlo + nb + 2 * (lane & 3);
    float m0 = -INFINITY, m1 = -INFINITY;
    #pragma unroll
    for (int t = 0; t < 18; ++t) {
        const int k0 = cb + t * 8, k1 = k0 + 1;
        if (k0 < r0 - cs || k0 > r0 + cs || k0 > jhi) sacc[t][0] = -INFINITY;
        if (k1 < r0 - cs || k1 > r0 + cs || k1 > jhi) sacc[t][1] = -INFINITY;
        if (k0 < r1 - cs || k0 > r1 + cs || k0 > jhi) sacc[t][2] = -INFINITY;
        if (k1 < r1 - cs || k1 > r1 + cs || k1 > jhi) sacc[t][3] = -INFINITY;
        m0 = fmaxf(m0, fmaxf(sacc[t][0], sacc[t][1]));
        m1 = fmaxf(m1, fmaxf(sacc[t][2], sacc[t][3]));
    }
    m0 = fmaxf(m0, __shfl_xor_sync(0xFFFFFFFFu, m0, 1));
    m0 = fmaxf(m0, __shfl_xor_sync(0xFFFFFFFFu, m0, 2));
    m1 = fmaxf(m1, __shfl_xor_sync(0xFFFFFFFFu, m1, 1));
    m1 = fmaxf(m1, __shfl_xor_sync(0xFFFFFFFFu, m1, 2));

    float sum0 = 0.0f, sum1 = 0.0f;
    uint32_t pf[18][2];
    #pragma unroll
    for (int t = 0; t < 18; ++t) {
        const float p00 = __expf(sacc[t][0] - m0);
        const float p01 = __expf(sacc[t][1] - m0);
        const float p10 = __expf(sacc[t][2] - m1);
        const float p11 = __expf(sacc[t][3] - m1);
        sum0 += p00 + p01;
        sum1 += p10 + p11;
        const __half2 h0 = __floats2half2_rn(p00, p01);
        const __half2 h1 = __floats2half2_rn(p10, p11);
        pf[t][0] = *reinterpret_cast<const uint32_t*>(&h0);
        pf[t][1] = *reinterpret_cast<const uint32_t*>(&h1);
    }
    sum0 += __shfl_xor_sync(0xFFFFFFFFu, sum0, 1);
    sum0 += __shfl_xor_sync(0xFFFFFFFFu, sum0, 2);
    sum1 += __shfl_xor_sync(0xFFFFFFFFu, sum1, 1);
    sum1 += __shfl_xor_sync(0xFFFFFFFFu, sum1, 2);
    const float inv0 = 1.0f / sum0;
    const float inv1 = 1.0f / sum1;

    float oacc[8][4] = {};
    #pragma unroll
    for (int j = 0; j < 9; ++j) {
        uint32_t pa[4] = {pf[2 * j][0], pf[2 * j][1], pf[2 * j + 1][0], pf[2 * j + 1][1]};
        #pragma unroll
        for (int ng = 0; ng < 4; ++ng) {
            uint32_t bf[4];
            ldsm4(bf, sV + ((uint32_t)(ng * 16 + bR) * VT_PAD + nb + j * 16 + bKo) * 2);
            mma_f32(oacc[ng * 2],     pa, &bf[0]);
            mma_f32(oacc[ng * 2 + 1], pa, &bf[2]);
        }
    }

    const size_t e0 = (size_t)(b * T + r0) * DIM + h * HDIM;
    const size_t e1 = (size_t)(b * T + r1) * DIM + h * HDIM;
    #pragma unroll
    for (int ni = 0; ni < 8; ++ni) {
        const int d = ni * 8 + 2 * (lane & 3);
        *reinterpret_cast<__half2*>(ctx + e0 + d) =
            __floats2half2_rn(oacc[ni][0] * inv0, oacc[ni][1] * inv0);
        *reinterpret_cast<__half2*>(ctx + e1 + d) =
            __floats2half2_rn(oacc[ni][2] * inv1, oacc[ni][3] * inv1);
    }
}

// ======================= launcher =======================
extern "C" void kernel_launch(void* const* d_in, const int* in_sizes, int n_in,
                              void* d_out, int out_size) {
    const float* x       = (const float*)d_in[0];
    const float* norm1_w = (const float*)d_in[1];
    const float* norm2_w = (const float*)d_in[2];
    const float* w_qkv   = (const float*)d_in[3];
    const float* w_out   = (const float*)d_in[4];
    const float* b_out   = (const float*)d_in[5];
    const float* w1      = (const float*)d_in[6];
    const float* b1      = (const float*)d_in[7];
    const float* w2      = (const float*)d_in[8];
    const float* b2      = (const float*)d_in[9];
    const int*   cs      = (const int*)d_in[10];
    float*       out     = (float*)d_out;

    const int BT = in_sizes[0] / DIM;   // 8192
    const int T  = T_SEQ;
    const int B  = BT / T;

    __half *wqkvT, *woutT, *w1T, *w2T, *xn, *ctx, *hh, *qkvh;
    float *x1;
    cudaGetSymbolAddress((void**)&wqkvT, g_wqkvT);
    cudaGetSymbolAddress((void**)&woutT, g_woutT);
    cudaGetSymbolAddress((void**)&w1T,   g_w1T);
    cudaGetSymbolAddress((void**)&w2T,   g_w2T);
    cudaGetSymbolAddress((void**)&xn,    g_xn);
    cudaGetSymbolAddress((void**)&ctx,   g_ctx);
    cudaGetSymbolAddress((void**)&hh,    g_hh);
    cudaGetSymbolAddress((void**)&qkvh,  g_qkvh);
    cudaGetSymbolAddress((void**)&x1,    g_x1);

    cudaFuncSetAttribute(gemm_mma<1>, cudaFuncAttributeMaxDynamicSharedMemorySize, GEMM_DSMEM);
    cudaFuncSetAttribute(gemm_mma<2>, cudaFuncAttributeMaxDynamicSharedMemorySize, GEMM_DSMEM);
    cudaFuncSetAttribute(gemm_mma<3>, cudaFuncAttributeMaxDynamicSharedMemorySize, GEMM_DSMEM);
    cudaFuncSetAttribute(attn_kernel, cudaFuncAttributeMaxDynamicSharedMemorySize, ATT_DSMEM);

    // 0. all weight preps in one launch
    wprep_all<<<3072, dim3(32, 8)>>>(w_qkv, wqkvT, w_out, woutT, w1, w1T, w2, w2T);

    // 1. xn = rmsnorm(x, norm1_w) -> f16
    rmsnorm_h_kernel<<<BT, 128>>>(x, norm1_w, xn);
    // 2. qkv = xn @ w_qkv -> f16
    gemm_mma<3><<<dim3((3 * DIM) / 128, BT / 128), 256, GEMM_DSMEM>>>(
        xn, wqkvT, nullptr, nullptr, nullptr, qkvh, BT, 3 * DIM, DIM);
    // 3. banded attention (tensor-core) -> ctx f16
    attn_kernel<<<dim3(T / 128, NHEAD, B), 256, ATT_DSMEM>>>(qkvh, ctx, cs, T);
    // 4. x1 = x + ctx @ w_out + b_out (fp32)
    gemm_mma<1><<<dim3(DIM / 128, BT / 128), 256, GEMM_DSMEM>>>(
        ctx, woutT, b_out, x, x1, nullptr, BT, DIM, DIM);
    // 5. xn = rmsnorm(x1, norm2_w) -> f16
    rmsnorm_h_kernel<<<BT, 128>>>(x1, norm2_w, xn);
    // 6. h = gelu(xn @ w1 + b1) -> f16
    gemm_mma<2><<<dim3(FFN_DIM / 128, BT / 128), 256, GEMM_DSMEM>>>(
        xn, w1T, b1, nullptr, nullptr, hh, BT, FFN_DIM, DIM);
    // 7. out = x1 + h @ w2 + b2
    gemm_mma<1><<<dim3(DIM / 128, BT / 128), 256, GEMM_DSMEM>>>(
        hh, w2T, b2, x1, out, nullptr, BT, DIM, FFN_DIM);
}